// round 7
// baseline (speedup 1.0000x reference)
#include <cuda_runtime.h>
#include <cuda_bf16.h>
#include <cstdint>
#include <cstddef>

#define N_USERS 100000
#define N_ITEMS 50000
#define NTOT    150000
#define D       64
#define NNZ     2000000
#define BSZ     16384
#define BITW    ((NTOT + 31) / 32)
#define TILE    1024
#define NBLK    ((NTOT + TILE - 1) / TILE)   // 147

// Scratch (allocation-free rule: __device__ globals, zero-init at load)
__device__ float    d_e1[(size_t)NTOT * D];
__device__ float    d_e2[(size_t)NTOT * D];
__device__ float    d_e3[(size_t)NTOT * D];
__device__ unsigned d_bitmap[BITW];
__device__ int      d_cnt[NTOT];             // re-zeroed by scan1 each call
__device__ int      d_start[NTOT + 1];
__device__ int      d_cursor[NTOT];
__device__ int      d_bsum[NBLK];
__device__ int      d_boff[NBLK];
__device__ int2     d_epack[NNZ];            // {col, bitcast(val)}

// ---------------------------------------------------------------------------
// Histogram (4 edges/thread, int4 loads). Also clears the bitmap for this
// call (mark_kernel runs after us on the same stream).
// ---------------------------------------------------------------------------
__global__ __launch_bounds__(256) void hist_kernel(const int4* __restrict__ grow4) {
    int i = blockIdx.x * blockDim.x + threadIdx.x;
    if (i < BITW) d_bitmap[i] = 0u;
    if (i < NNZ / 4) {
        int4 r = __ldg(grow4 + i);
        atomicAdd(&d_cnt[r.x], 1);
        atomicAdd(&d_cnt[r.y], 1);
        atomicAdd(&d_cnt[r.z], 1);
        atomicAdd(&d_cnt[r.w], 1);
    }
}

// Mark rows needed by the final gather (users and N_USERS+items)
__global__ void mark_kernel(const int* __restrict__ users,
                            const int* __restrict__ items) {
    int i = blockIdx.x * blockDim.x + threadIdx.x;
    if (i < BSZ) {
        int r = users[i];
        atomicOr(&d_bitmap[r >> 5], 1u << (r & 31));
    } else if (i < 2 * BSZ) {
        int r = N_USERS + items[i - BSZ];
        atomicOr(&d_bitmap[r >> 5], 1u << (r & 31));
    }
}

// ---------------------------------------------------------------------------
// Scan: per-block exclusive scan over TILE=1024 (256 thr x 4), block sums out.
// Re-zeroes d_cnt after reading (so no separate reset kernel is needed).
// ---------------------------------------------------------------------------
__global__ __launch_bounds__(256) void scan1_kernel() {
    __shared__ int sh[256];
    int t = threadIdx.x, b = blockIdx.x;
    int base = b * TILE + t * 4;
    int v[4];
#pragma unroll
    for (int i = 0; i < 4; i++) {
        if (base + i < NTOT) { v[i] = d_cnt[base + i]; d_cnt[base + i] = 0; }
        else v[i] = 0;
    }
    int s = v[0] + v[1] + v[2] + v[3];
    sh[t] = s;
    __syncthreads();
    for (int off = 1; off < 256; off <<= 1) {
        int x = (t >= off) ? sh[t - off] : 0;
        __syncthreads();
        sh[t] += x;
        __syncthreads();
    }
    int run = sh[t] - s;
#pragma unroll
    for (int i = 0; i < 4; i++) {
        if (base + i < NTOT) d_start[base + i] = run;
        run += v[i];
    }
    if (t == 255) d_bsum[b] = sh[255];
}

__global__ __launch_bounds__(256) void scan2_kernel() {
    __shared__ int sh[256];
    int t = threadIdx.x;
    int v = (t < NBLK) ? d_bsum[t] : 0;
    sh[t] = v;
    __syncthreads();
    for (int off = 1; off < 256; off <<= 1) {
        int x = (t >= off) ? sh[t - off] : 0;
        __syncthreads();
        sh[t] += x;
        __syncthreads();
    }
    if (t < NBLK) d_boff[t] = sh[t] - v;
}

__global__ void scan3_kernel() {
    int i = blockIdx.x * blockDim.x + threadIdx.x;
    if (i < NTOT) {
        int s = d_start[i] + d_boff[i / TILE];
        d_start[i]  = s;
        d_cursor[i] = s;
    }
    if (i == NTOT) d_start[NTOT] = NNZ;
}

// Scatter 4 edges/thread (int4/float4 loads; packed {col,val} stores)
__global__ __launch_bounds__(256) void scatter_kernel(const int4*   __restrict__ grow4,
                                                      const int4*   __restrict__ gcol4,
                                                      const float4* __restrict__ gval4) {
    int i = blockIdx.x * blockDim.x + threadIdx.x;
    if (i >= NNZ / 4) return;
    int4   r = __ldg(grow4 + i);
    int4   c = __ldg(gcol4 + i);
    float4 v = __ldg(gval4 + i);
    int p;
    p = atomicAdd(&d_cursor[r.x], 1); d_epack[p] = make_int2(c.x, __float_as_int(v.x));
    p = atomicAdd(&d_cursor[r.y], 1); d_epack[p] = make_int2(c.y, __float_as_int(v.y));
    p = atomicAdd(&d_cursor[r.z], 1); d_epack[p] = make_int2(c.z, __float_as_int(v.z));
    p = atomicAdd(&d_cursor[r.w], 1); d_epack[p] = make_int2(c.w, __float_as_int(v.w));
}

// ---------------------------------------------------------------------------
// Row-parallel SpMM over CSR: ONE ROW PER WARP, 32 lanes x float2.
// No intra-warp divergence; 4-deep gather pipeline + 2-wide tail.
// MODE 0: src = concat(emb_user, emb_item) -> d_e1
// MODE 1: d_e1 -> d_e2
// MODE 2: d_e2 -> d_e3, whole rows skipped unless needed (bitmap)
// ---------------------------------------------------------------------------
template <int MODE>
__device__ __forceinline__ const float* src_row(int col,
                                                const float* __restrict__ embU,
                                                const float* __restrict__ embI) {
    if (MODE == 0)
        return (col < N_USERS) ? (embU + (size_t)col * D)
                               : (embI + (size_t)(col - N_USERS) * D);
    else if (MODE == 1)
        return d_e1 + (size_t)col * D;
    else
        return d_e2 + (size_t)col * D;
}

template <int MODE>
__global__ __launch_bounds__(256) void spmm_csr_kernel(
        const float* __restrict__ embU,
        const float* __restrict__ embI) {
    unsigned r = (blockIdx.x * blockDim.x + threadIdx.x) >> 5;
    if (r >= NTOT) return;
    if (MODE == 2) {
        if (!((d_bitmap[r >> 5] >> (r & 31)) & 1u)) return;
    }
    unsigned c2 = (threadIdx.x & 31u) * 2u;   // float offset within 64-wide row

    int j   = __ldg(d_start + r);
    int end = __ldg(d_start + r + 1);

    float2 acc = make_float2(0.f, 0.f);

    for (; j + 4 <= end; j += 4) {
        int2 p0 = __ldg(d_epack + j);
        int2 p1 = __ldg(d_epack + j + 1);
        int2 p2 = __ldg(d_epack + j + 2);
        int2 p3 = __ldg(d_epack + j + 3);
        float2 x0 = *reinterpret_cast<const float2*>(src_row<MODE>(p0.x, embU, embI) + c2);
        float2 x1 = *reinterpret_cast<const float2*>(src_row<MODE>(p1.x, embU, embI) + c2);
        float2 x2 = *reinterpret_cast<const float2*>(src_row<MODE>(p2.x, embU, embI) + c2);
        float2 x3 = *reinterpret_cast<const float2*>(src_row<MODE>(p3.x, embU, embI) + c2);
        float v0 = __int_as_float(p0.y), v1 = __int_as_float(p1.y);
        float v2 = __int_as_float(p2.y), v3 = __int_as_float(p3.y);
        acc.x = fmaf(v0, x0.x, acc.x); acc.y = fmaf(v0, x0.y, acc.y);
        acc.x = fmaf(v1, x1.x, acc.x); acc.y = fmaf(v1, x1.y, acc.y);
        acc.x = fmaf(v2, x2.x, acc.x); acc.y = fmaf(v2, x2.y, acc.y);
        acc.x = fmaf(v3, x3.x, acc.x); acc.y = fmaf(v3, x3.y, acc.y);
    }
    if (j + 2 <= end) {
        int2 p0 = __ldg(d_epack + j);
        int2 p1 = __ldg(d_epack + j + 1);
        float2 x0 = *reinterpret_cast<const float2*>(src_row<MODE>(p0.x, embU, embI) + c2);
        float2 x1 = *reinterpret_cast<const float2*>(src_row<MODE>(p1.x, embU, embI) + c2);
        float v0 = __int_as_float(p0.y), v1 = __int_as_float(p1.y);
        acc.x = fmaf(v0, x0.x, acc.x); acc.y = fmaf(v0, x0.y, acc.y);
        acc.x = fmaf(v1, x1.x, acc.x); acc.y = fmaf(v1, x1.y, acc.y);
        j += 2;
    }
    if (j < end) {
        int2 p = __ldg(d_epack + j);
        float2 x = *reinterpret_cast<const float2*>(src_row<MODE>(p.x, embU, embI) + c2);
        float v = __int_as_float(p.y);
        acc.x = fmaf(v, x.x, acc.x); acc.y = fmaf(v, x.y, acc.y);
    }

    float* dst = (MODE == 0) ? d_e1 : (MODE == 1) ? d_e2 : d_e3;
    *reinterpret_cast<float2*>(dst + (size_t)r * D + c2) = acc;
}

// ---------------------------------------------------------------------------
// Final head: gather light embeddings, W_u/W_i matvecs, softmax, sigmoid, dot.
// ---------------------------------------------------------------------------
__global__ __launch_bounds__(64) void final_kernel(
    const float* __restrict__ embU, const float* __restrict__ embI,
    const float* __restrict__ wU,   const float* __restrict__ wI,
    const float* __restrict__ x1,   const float* __restrict__ x0,
    const int*   __restrict__ users,const int*   __restrict__ items,
    const int*   __restrict__ xij,  float*       __restrict__ out) {
    __shared__ float sWu[D * D];
    __shared__ float sWi[D * D];
    __shared__ float sa[D * 64];

    int tid = threadIdx.x;
    for (int i = tid; i < D * D; i += 64) {
        sWu[i] = wU[i];
        sWi[i] = wI[i];
    }
    __syncthreads();

    int b  = blockIdx.x * 64 + tid;
    int u  = users[b];
    int it = items[b];

    float vec[D];

    {
        const float* p0 = embU + (size_t)u * D;
        const float* p1 = d_e1 + (size_t)u * D;
        const float* p2 = d_e2 + (size_t)u * D;
        const float* p3 = d_e3 + (size_t)u * D;
#pragma unroll
        for (int d = 0; d < D; d++)
            vec[d] = 0.25f * (p0[d] + p1[d] + p2[d] + p3[d]);
    }

    float amax = -1e30f;
    for (int j = 0; j < D; j++) {
        const float* w = sWu + j * D;
        float a = 0.f;
#pragma unroll
        for (int d = 0; d < D; d++) a = fmaf(vec[d], w[d], a);
        sa[j * 64 + tid] = a;
        amax = fmaxf(amax, a);
    }
    float ssum = 0.f;
    for (int j = 0; j < D; j++) {
        float ex = __expf(sa[j * 64 + tid] - amax);
        sa[j * 64 + tid] = ex;
        ssum += ex;
    }
    float scale = 0.5f / ssum;   // (1 - hx) * softmax

    {
        size_t ir = (size_t)(N_USERS + it) * D;
        const float* q0 = embI + (size_t)it * D;
#pragma unroll
        for (int d = 0; d < D; d++)
            vec[d] = 0.25f * (q0[d] + d_e1[ir + d] + d_e2[ir + d] + d_e3[ir + d]);
    }

    float res = 0.f;
    for (int j = 0; j < D; j++) {
        const float* w = sWi + j * D;
        float a = 0.f;
#pragma unroll
        for (int d = 0; d < D; d++) a = fmaf(vec[d], w[d], a);
        float sg = 1.f / (1.f + __expf(-a));
        res += sa[j * 64 + tid] * scale * sg;
    }

    float xe = (xij[b] > 0) ? x1[it] : x0[it];
    res += 0.5f * (1.f / (1.f + __expf(-xe)));

    out[b] = res;
}

// ---------------------------------------------------------------------------
extern "C" void kernel_launch(void* const* d_in, const int* in_sizes, int n_in,
                              void* d_out, int out_size) {
    const float* embU  = (const float*)d_in[0];
    const float* embI  = (const float*)d_in[1];
    const float* wU    = (const float*)d_in[2];
    const float* wI    = (const float*)d_in[3];
    const float* x1    = (const float*)d_in[4];
    const float* x0    = (const float*)d_in[5];
    const float* gval  = (const float*)d_in[6];
    const int*   grow  = (const int*)d_in[7];
    const int*   gcol  = (const int*)d_in[8];
    const int*   users = (const int*)d_in[9];
    const int*   items = (const int*)d_in[10];
    const int*   xij   = (const int*)d_in[11];
    float*       out   = (float*)d_out;

    (void)in_sizes; (void)n_in; (void)out_size;

    // CSR build (d_cnt is zero on entry: .bss init on first call, re-zeroed
    // by scan1 on every call thereafter; bitmap cleared inside hist_kernel)
    hist_kernel<<<(NNZ / 4 + 255) / 256, 256>>>((const int4*)grow);
    mark_kernel<<<(2 * BSZ + 255) / 256, 256>>>(users, items);
    scan1_kernel<<<NBLK, 256>>>();
    scan2_kernel<<<1, 256>>>();
    scan3_kernel<<<(NTOT + 1 + 255) / 256, 256>>>();
    scatter_kernel<<<(NNZ / 4 + 255) / 256, 256>>>((const int4*)grow,
                                                   (const int4*)gcol,
                                                   (const float4*)gval);

    // Three row-parallel SpMM layers (one row per warp)
    const unsigned total  = (unsigned)NTOT * 32u;
    const unsigned blocks = (total + 255) / 256;
    spmm_csr_kernel<0><<<blocks, 256>>>(embU, embI);
    spmm_csr_kernel<1><<<blocks, 256>>>(embU, embI);
    spmm_csr_kernel<2><<<blocks, 256>>>(embU, embI);

    // Final head
    final_kernel<<<BSZ / 64, 64>>>(embU, embI, wU, wI, x1, x0,
                                   users, items, xij, out);
}

// round 10
// speedup vs baseline: 1.3709x; 1.3709x over previous
#include <cuda_runtime.h>
#include <cuda_fp16.h>
#include <cstdint>
#include <cstddef>

#define N_USERS 100000
#define N_ITEMS 50000
#define NTOT    150000
#define D       64
#define NNZ     2000000
#define BSZ     16384
#define BITW    ((NTOT + 31) / 32)
#define TILE    1024
#define NBLK    ((NTOT + TILE - 1) / TILE)   // 147
#define RW      (D / 4)                      // uint2 (4 halves) per row = 16

// Scratch (allocation-free rule: __device__ globals, zero-init at load)
// Feature layers stored as fp16, packed 4 halves per uint2 (8B aligned).
__device__ uint2    d_h0[(size_t)NTOT * RW];   // fp16 copy of concat(embU, embI)
__device__ uint2    d_h1[(size_t)NTOT * RW];
__device__ uint2    d_h2[(size_t)NTOT * RW];
__device__ uint2    d_h3[(size_t)NTOT * RW];
__device__ unsigned d_bitmap[BITW];
__device__ int      d_cnt[NTOT];               // re-zeroed by scan1 each call
__device__ int      d_start[NTOT + 1];
__device__ int      d_cursor[NTOT];
__device__ int      d_bsum[NBLK];
__device__ int2     d_epack[NNZ];              // {col, bitcast(val)}

// ---------------------------------------------------------------------------
// Kernel 1: histogram (4 edges/thread, int4) + bitmap clear + fp32->fp16
// conversion of e0 (grid-stride).
// ---------------------------------------------------------------------------
__global__ __launch_bounds__(256) void hist_kernel(const int4*   __restrict__ grow4,
                                                   const float2* __restrict__ embU2,
                                                   const float2* __restrict__ embI2) {
    int i = blockIdx.x * blockDim.x + threadIdx.x;
    if (i < BITW) d_bitmap[i] = 0u;
    if (i < NNZ / 4) {
        int4 r = __ldg(grow4 + i);
        atomicAdd(&d_cnt[r.x], 1);
        atomicAdd(&d_cnt[r.y], 1);
        atomicAdd(&d_cnt[r.z], 1);
        atomicAdd(&d_cnt[r.w], 1);
    }
    // e0 conversion: one uint2 = 4 halves = 2 float2 loads
    const int HTOT = NTOT * RW;                 // 2.4M uint2
    const int USPLIT = N_USERS * RW;
    int nth = gridDim.x * blockDim.x;
    for (int k = i; k < HTOT; k += nth) {
        float2 a, b;
        if (k < USPLIT) { a = __ldg(embU2 + 2 * k);          b = __ldg(embU2 + 2 * k + 1); }
        else            { a = __ldg(embI2 + 2 * (k - USPLIT)); b = __ldg(embI2 + 2 * (k - USPLIT) + 1); }
        __half2 h0 = __float22half2_rn(a);
        __half2 h1 = __float22half2_rn(b);
        uint2 q;
        q.x = *reinterpret_cast<unsigned*>(&h0);
        q.y = *reinterpret_cast<unsigned*>(&h1);
        d_h0[k] = q;
    }
}

// ---------------------------------------------------------------------------
// Kernel 2: per-block exclusive scan over TILE=1024 rows (256 thr x 4);
// re-zeroes d_cnt; also marks the needed-row bitmap (folded mark_kernel).
// ---------------------------------------------------------------------------
__global__ __launch_bounds__(256) void scan1_kernel(const int* __restrict__ users,
                                                    const int* __restrict__ items) {
    __shared__ int sh[256];
    int t = threadIdx.x, b = blockIdx.x;

    // folded mark: 147*256 = 37632 >= 2*BSZ
    int gi = b * 256 + t;
    if (gi < BSZ) {
        int r = users[gi];
        atomicOr(&d_bitmap[r >> 5], 1u << (r & 31));
    } else if (gi < 2 * BSZ) {
        int r = N_USERS + items[gi - BSZ];
        atomicOr(&d_bitmap[r >> 5], 1u << (r & 31));
    }

    int base = b * TILE + t * 4;
    int v[4];
#pragma unroll
    for (int i = 0; i < 4; i++) {
        if (base + i < NTOT) { v[i] = d_cnt[base + i]; d_cnt[base + i] = 0; }
        else v[i] = 0;
    }
    int s = v[0] + v[1] + v[2] + v[3];
    sh[t] = s;
    __syncthreads();
    for (int off = 1; off < 256; off <<= 1) {
        int x = (t >= off) ? sh[t - off] : 0;
        __syncthreads();
        sh[t] += x;
        __syncthreads();
    }
    int run = sh[t] - s;
#pragma unroll
    for (int i = 0; i < 4; i++) {
        if (base + i < NTOT) d_start[base + i] = run;
        run += v[i];
    }
    if (t == 255) d_bsum[b] = sh[255];
}

// ---------------------------------------------------------------------------
// Kernel 3: fused scan2+scan3. Each 256-row block reduces the bsums of all
// preceding tiles itself, then finalizes d_start/d_cursor.
// ---------------------------------------------------------------------------
__global__ __launch_bounds__(256) void scan23_kernel() {
    __shared__ int sh[256];
    int t = threadIdx.x;
    int i = blockIdx.x * 256 + t;
    int tile = (int)(blockIdx.x >> 2);          // 4 blocks per TILE

    sh[t] = (t < tile && t < NBLK) ? d_bsum[t] : 0;
    __syncthreads();
    for (int off = 128; off; off >>= 1) {
        if (t < off) sh[t] += sh[t + off];
        __syncthreads();
    }
    int boff = sh[0];

    if (i < NTOT) {
        int s = d_start[i] + boff;
        d_start[i]  = s;
        d_cursor[i] = s;
    }
    if (i == 0) d_start[NTOT] = NNZ;
}

// ---------------------------------------------------------------------------
// Kernel 4: scatter 4 edges/thread into packed {col,val}
// ---------------------------------------------------------------------------
__global__ __launch_bounds__(256) void scatter_kernel(const int4*   __restrict__ grow4,
                                                      const int4*   __restrict__ gcol4,
                                                      const float4* __restrict__ gval4) {
    int i = blockIdx.x * blockDim.x + threadIdx.x;
    if (i >= NNZ / 4) return;
    int4   r = __ldg(grow4 + i);
    int4   c = __ldg(gcol4 + i);
    float4 v = __ldg(gval4 + i);
    int p;
    p = atomicAdd(&d_cursor[r.x], 1); d_epack[p] = make_int2(c.x, __float_as_int(v.x));
    p = atomicAdd(&d_cursor[r.y], 1); d_epack[p] = make_int2(c.y, __float_as_int(v.y));
    p = atomicAdd(&d_cursor[r.z], 1); d_epack[p] = make_int2(c.z, __float_as_int(v.z));
    p = atomicAdd(&d_cursor[r.w], 1); d_epack[p] = make_int2(c.w, __float_as_int(v.w));
}

// ---------------------------------------------------------------------------
// Row-parallel SpMM over CSR on fp16 features: 16 lanes per row (2 rows per
// warp), each lane covers 4 feature columns (one uint2 = 8B per gather).
// fp32 accumulation; 4-deep pipelined batches with clamped-index predication
// (no serial tail). MODE: 0: h0->h1, 1: h1->h2, 2: h2->h3 (bitmap-pruned).
// ---------------------------------------------------------------------------
template <int MODE>
__global__ __launch_bounds__(256) void spmm_csr_kernel() {
    unsigned gid = blockIdx.x * blockDim.x + threadIdx.x;
    unsigned r   = gid >> 4;
    if (r >= NTOT) return;
    if (MODE == 2) {
        if (!((d_bitmap[r >> 5] >> (r & 31)) & 1u)) return;
    }
    unsigned lane = gid & 15u;                  // uint2 index within row

    const uint2* __restrict__ src = (MODE == 0) ? d_h0 : (MODE == 1) ? d_h1 : d_h2;
    uint2* __restrict__ dst       = (MODE == 0) ? d_h1 : (MODE == 1) ? d_h2 : d_h3;

    int j   = __ldg(d_start + r);
    int end = __ldg(d_start + r + 1);
    if (j >= end) {   // empty row: still must write zeros
        dst[(size_t)r * RW + lane] = make_uint2(0u, 0u);
        return;
    }

    float4 acc = make_float4(0.f, 0.f, 0.f, 0.f);

    for (; j < end; j += 4) {
        int i0 = j;
        int i1 = (j + 1 < end) ? j + 1 : j;
        int i2 = (j + 2 < end) ? j + 2 : j;
        int i3 = (j + 3 < end) ? j + 3 : j;
        int2 p0 = __ldg(d_epack + i0);
        int2 p1 = __ldg(d_epack + i1);
        int2 p2 = __ldg(d_epack + i2);
        int2 p3 = __ldg(d_epack + i3);
        uint2 q0 = __ldg(src + (size_t)p0.x * RW + lane);
        uint2 q1 = __ldg(src + (size_t)p1.x * RW + lane);
        uint2 q2 = __ldg(src + (size_t)p2.x * RW + lane);
        uint2 q3 = __ldg(src + (size_t)p3.x * RW + lane);
        float v0 = __int_as_float(p0.y);
        float v1 = (j + 1 < end) ? __int_as_float(p1.y) : 0.f;
        float v2 = (j + 2 < end) ? __int_as_float(p2.y) : 0.f;
        float v3 = (j + 3 < end) ? __int_as_float(p3.y) : 0.f;

        float2 a, b;
        a = __half22float2(*reinterpret_cast<__half2*>(&q0.x));
        b = __half22float2(*reinterpret_cast<__half2*>(&q0.y));
        acc.x = fmaf(v0, a.x, acc.x); acc.y = fmaf(v0, a.y, acc.y);
        acc.z = fmaf(v0, b.x, acc.z); acc.w = fmaf(v0, b.y, acc.w);
        a = __half22float2(*reinterpret_cast<__half2*>(&q1.x));
        b = __half22float2(*reinterpret_cast<__half2*>(&q1.y));
        acc.x = fmaf(v1, a.x, acc.x); acc.y = fmaf(v1, a.y, acc.y);
        acc.z = fmaf(v1, b.x, acc.z); acc.w = fmaf(v1, b.y, acc.w);
        a = __half22float2(*reinterpret_cast<__half2*>(&q2.x));
        b = __half22float2(*reinterpret_cast<__half2*>(&q2.y));
        acc.x = fmaf(v2, a.x, acc.x); acc.y = fmaf(v2, a.y, acc.y);
        acc.z = fmaf(v2, b.x, acc.z); acc.w = fmaf(v2, b.y, acc.w);
        a = __half22float2(*reinterpret_cast<__half2*>(&q3.x));
        b = __half22float2(*reinterpret_cast<__half2*>(&q3.y));
        acc.x = fmaf(v3, a.x, acc.x); acc.y = fmaf(v3, a.y, acc.y);
        acc.z = fmaf(v3, b.x, acc.z); acc.w = fmaf(v3, b.y, acc.w);
    }

    __half2 h0 = __floats2half2_rn(acc.x, acc.y);
    __half2 h1 = __floats2half2_rn(acc.z, acc.w);
    uint2 q;
    q.x = *reinterpret_cast<unsigned*>(&h0);
    q.y = *reinterpret_cast<unsigned*>(&h1);
    dst[(size_t)r * RW + lane] = q;
}

// ---------------------------------------------------------------------------
// Final head: gather light embeddings (fp32 e0 + fp16 e1..e3), W_u/W_i
// matvecs, softmax, sigmoid, weighted dot.
// ---------------------------------------------------------------------------
__global__ __launch_bounds__(64) void final_kernel(
    const float* __restrict__ embU, const float* __restrict__ embI,
    const float* __restrict__ wU,   const float* __restrict__ wI,
    const float* __restrict__ x1,   const float* __restrict__ x0,
    const int*   __restrict__ users,const int*   __restrict__ items,
    const int*   __restrict__ xij,  float*       __restrict__ out) {
    __shared__ float sWu[D * D];
    __shared__ float sWi[D * D];
    __shared__ float sa[D * 64];

    int tid = threadIdx.x;
    for (int i = tid; i < D * D; i += 64) {
        sWu[i] = wU[i];
        sWi[i] = wI[i];
    }
    __syncthreads();

    int b  = blockIdx.x * 64 + tid;
    int u  = users[b];
    int it = items[b];

    const __half* h1 = reinterpret_cast<const __half*>(d_h1);
    const __half* h2 = reinterpret_cast<const __half*>(d_h2);
    const __half* h3 = reinterpret_cast<const __half*>(d_h3);

    float vec[D];

    {
        const float* p0 = embU + (size_t)u * D;
        size_t ur = (size_t)u * D;
#pragma unroll
        for (int d = 0; d < D; d++)
            vec[d] = 0.25f * (p0[d] + __half2float(h1[ur + d])
                                    + __half2float(h2[ur + d])
                                    + __half2float(h3[ur + d]));
    }

    float amax = -1e30f;
    for (int j = 0; j < D; j++) {
        const float* w = sWu + j * D;
        float a = 0.f;
#pragma unroll
        for (int d = 0; d < D; d++) a = fmaf(vec[d], w[d], a);
        sa[j * 64 + tid] = a;
        amax = fmaxf(amax, a);
    }
    float ssum = 0.f;
    for (int j = 0; j < D; j++) {
        float ex = __expf(sa[j * 64 + tid] - amax);
        sa[j * 64 + tid] = ex;
        ssum += ex;
    }
    float scale = 0.5f / ssum;   // (1 - hx) * softmax

    {
        size_t ir = (size_t)(N_USERS + it) * D;
        const float* q0 = embI + (size_t)it * D;
#pragma unroll
        for (int d = 0; d < D; d++)
            vec[d] = 0.25f * (q0[d] + __half2float(h1[ir + d])
                                    + __half2float(h2[ir + d])
                                    + __half2float(h3[ir + d]));
    }

    float res = 0.f;
    for (int j = 0; j < D; j++) {
        const float* w = sWi + j * D;
        float a = 0.f;
#pragma unroll
        for (int d = 0; d < D; d++) a = fmaf(vec[d], w[d], a);
        float sg = 1.f / (1.f + __expf(-a));
        res += sa[j * 64 + tid] * scale * sg;
    }

    float xe = (xij[b] > 0) ? x1[it] : x0[it];
    res += 0.5f * (1.f / (1.f + __expf(-xe)));

    out[b] = res;
}

// ---------------------------------------------------------------------------
extern "C" void kernel_launch(void* const* d_in, const int* in_sizes, int n_in,
                              void* d_out, int out_size) {
    const float* embU  = (const float*)d_in[0];
    const float* embI  = (const float*)d_in[1];
    const float* wU    = (const float*)d_in[2];
    const float* wI    = (const float*)d_in[3];
    const float* x1    = (const float*)d_in[4];
    const float* x0    = (const float*)d_in[5];
    const float* gval  = (const float*)d_in[6];
    const int*   grow  = (const int*)d_in[7];
    const int*   gcol  = (const int*)d_in[8];
    const int*   users = (const int*)d_in[9];
    const int*   items = (const int*)d_in[10];
    const int*   xij   = (const int*)d_in[11];
    float*       out   = (float*)d_out;

    (void)in_sizes; (void)n_in; (void)out_size;

    // CSR build + e0 fp16 conversion (d_cnt zero on entry: .bss init first
    // call, re-zeroed by scan1 each call; bitmap cleared in hist)
    hist_kernel<<<(NNZ / 4 + 255) / 256, 256>>>((const int4*)grow,
                                                (const float2*)embU,
                                                (const float2*)embI);
    scan1_kernel<<<NBLK, 256>>>(users, items);
    scan23_kernel<<<(NTOT + 255) / 256, 256>>>();
    scatter_kernel<<<(NNZ / 4 + 255) / 256, 256>>>((const int4*)grow,
                                                   (const int4*)gcol,
                                                   (const float4*)gval);

    // Three row-parallel SpMM layers (16 lanes per row, fp16 features)
    const unsigned total  = (unsigned)NTOT * 16u;
    const unsigned blocks = (total + 255) / 256;
    spmm_csr_kernel<0><<<blocks, 256>>>();
    spmm_csr_kernel<1><<<blocks, 256>>>();
    spmm_csr_kernel<2><<<blocks, 256>>>();

    // Final head
    final_kernel<<<BSZ / 64, 64>>>(embU, embI, wU, wI, x1, x0,
                                   users, items, xij, out);
}